// round 2
// baseline (speedup 1.0000x reference)
#include <cuda_runtime.h>

// ---------------------------------------------------------------------------
// Masked multi-level MSE loss (B=16, C=256, T=128, S in {80,40,20}):
//   L = mean_l [ sum((M_l * (p_l - t_l))^2) / (C * sum(M_l)) ]
//
// 2-kernel pipeline:
//   1) mask_kernel: rasterize boxes -> per-level uint8 masks (no atomics)
//   2) reduce_kernel: streams pred/true, accumulates sum-of-squares AND the
//      mask-byte count (== C*sum(M) exactly, since each mask byte is read C
//      times); last block finalizes into d_out (self-resetting ticket).
// ---------------------------------------------------------------------------

#define NB 16
#define NT 128
#define NC 256
#define GRID_BLOCKS 1184   // 148 SMs * 8
#define BLOCK_THREADS 256

__device__ unsigned char g_mask0[NB * 80 * 80];
__device__ unsigned char g_mask1[NB * 40 * 40];
__device__ unsigned char g_mask2[NB * 20 * 20];

__device__ float g_pa[3][GRID_BLOCKS];   // per-block sum-of-squares partials
__device__ int   g_pc[3][GRID_BLOCKS];   // per-block mask-byte-count partials
__device__ unsigned g_ticket = 0;        // last-block finalize ticket (self-resetting)

// ---------------------------------------------------------------------------
// Rasterize all T boxes into per-level masks. gridDim.y = level.
__global__ void mask_kernel(const float* __restrict__ bboxes,
                            const int* __restrict__ batch_idx) {
    const int lvl = blockIdx.y;
    const int S = (lvl == 0) ? 80 : (lvl == 1) ? 40 : 20;
    const int cells = NB * S * S;
    if ((int)(blockIdx.x * blockDim.x) >= cells) return;

    __shared__ short sxl[NT], sxr[NT], syt[NT], syd[NT];
    __shared__ signed char sbi[NT];

    if (threadIdx.x < NT) {
        const int t = threadIdx.x;
        const float fS = (float)S;
        int xc = (int)floorf(bboxes[t * 4 + 0] * fS);
        int yc = (int)floorf(bboxes[t * 4 + 1] * fS);
        int w  = (int)floorf(bboxes[t * 4 + 2] * fS);
        int h  = (int)floorf(bboxes[t * 4 + 3] * fS);
        sxl[t] = (short)max(xc - w / 2, 0);
        syt[t] = (short)max(yc - h / 2, 0);
        sxr[t] = (short)min(xc + w / 2, S - 1);
        syd[t] = (short)min(yc + h / 2, S - 1);
        sbi[t] = (signed char)batch_idx[t];
    }
    __syncthreads();

    const int idx = blockIdx.x * blockDim.x + threadIdx.x;
    if (idx < cells) {
        const int b = idx / (S * S);
        const int rr = idx % (S * S);
        const int y = rr / S;
        const int x = rr % S;
        int m = 0;
#pragma unroll 4
        for (int t = 0; t < NT; t++) {
            m |= ((int)sbi[t] == b) &
                 (x >= (int)sxl[t]) & (x <= (int)sxr[t]) &
                 (y >= (int)syt[t]) & (y <= (int)syd[t]);
        }
        unsigned char* mk = (lvl == 0) ? g_mask0 : (lvl == 1) ? g_mask1 : g_mask2;
        mk[idx] = (unsigned char)m;
    }
}

// ---------------------------------------------------------------------------
__device__ __forceinline__ float block_sum_f(float v, float* sm) {
#pragma unroll
    for (int o = 16; o; o >>= 1) v += __shfl_down_sync(0xffffffffu, v, o);
    const int lane = threadIdx.x & 31, warp = threadIdx.x >> 5;
    if (lane == 0) sm[warp] = v;
    __syncthreads();
    v = (threadIdx.x < (BLOCK_THREADS / 32)) ? sm[threadIdx.x] : 0.f;
    if (warp == 0) {
#pragma unroll
        for (int o = 16; o; o >>= 1) v += __shfl_down_sync(0xffffffffu, v, o);
    }
    __syncthreads();
    return v;
}

__device__ __forceinline__ int block_sum_i(int v, int* sm) {
#pragma unroll
    for (int o = 16; o; o >>= 1) v += __shfl_down_sync(0xffffffffu, v, o);
    const int lane = threadIdx.x & 31, warp = threadIdx.x >> 5;
    if (lane == 0) sm[warp] = v;
    __syncthreads();
    v = (threadIdx.x < (BLOCK_THREADS / 32)) ? sm[threadIdx.x] : 0;
    if (warp == 0) {
#pragma unroll
        for (int o = 16; o; o >>= 1) v += __shfl_down_sync(0xffffffffu, v, o);
    }
    __syncthreads();
    return v;
}

// ---------------------------------------------------------------------------
template <int S>
__device__ __forceinline__ void level_sumsq(const float4* __restrict__ p,
                                            const float4* __restrict__ q,
                                            const unsigned char* __restrict__ mask,
                                            unsigned gid, unsigned stride,
                                            float& acc_out, int& cnt_out) {
    constexpr unsigned S4  = (unsigned)S / 4;
    constexpr unsigned CH4 = (unsigned)S * S4;        // float4 per (b,c) image
    constexpr unsigned B4  = (unsigned)NC * CH4;      // float4 per batch
    constexpr unsigned N4  = (unsigned)NB * B4;       // total float4
    float acc = 0.f;
    int cnt = 0;
    for (unsigned i = gid; i < N4; i += stride) {
        const unsigned b = i / B4;
        const unsigned r = i % CH4;
        const uchar4 m = *(const uchar4*)(mask + b * (unsigned)(S * S) + 4u * r);
        const int ms = (int)m.x + (int)m.y + (int)m.z + (int)m.w;
        cnt += ms;
        if (ms != 0) {
            const float4 a = __ldg(&p[i]);
            const float4 c = __ldg(&q[i]);
            const float d0 = a.x - c.x, d1 = a.y - c.y;
            const float d2 = a.z - c.z, d3 = a.w - c.w;
            acc += (float)m.x * d0 * d0 + (float)m.y * d1 * d1 +
                   (float)m.z * d2 * d2 + (float)m.w * d3 * d3;
        }
    }
    acc_out = acc;
    cnt_out = cnt;
}

// ---------------------------------------------------------------------------
__global__ void __launch_bounds__(BLOCK_THREADS)
reduce_kernel(const float4* __restrict__ p0, const float4* __restrict__ t0,
              const float4* __restrict__ p1, const float4* __restrict__ t1,
              const float4* __restrict__ p2, const float4* __restrict__ t2,
              float* __restrict__ out) {
    const unsigned gid = blockIdx.x * BLOCK_THREADS + threadIdx.x;
    const unsigned stride = GRID_BLOCKS * BLOCK_THREADS;

    float a0, a1, a2;
    int c0, c1, c2;
    level_sumsq<80>(p0, t0, g_mask0, gid, stride, a0, c0);
    level_sumsq<40>(p1, t1, g_mask1, gid, stride, a1, c1);
    level_sumsq<20>(p2, t2, g_mask2, gid, stride, a2, c2);

    __shared__ float smf[32];
    __shared__ int smi[32];
    a0 = block_sum_f(a0, smf);
    a1 = block_sum_f(a1, smf);
    a2 = block_sum_f(a2, smf);
    c0 = block_sum_i(c0, smi);
    c1 = block_sum_i(c1, smi);
    c2 = block_sum_i(c2, smi);

    __shared__ bool s_last;
    if (threadIdx.x == 0) {
        g_pa[0][blockIdx.x] = a0;
        g_pa[1][blockIdx.x] = a1;
        g_pa[2][blockIdx.x] = a2;
        g_pc[0][blockIdx.x] = c0;
        g_pc[1][blockIdx.x] = c1;
        g_pc[2][blockIdx.x] = c2;
        __threadfence();
        unsigned n = atomicAdd(&g_ticket, 1u);
        s_last = (n == GRID_BLOCKS - 1);
    }
    __syncthreads();
    if (!s_last) return;

    // --- finalize (last block only) ---
    float fa0 = 0.f, fa1 = 0.f, fa2 = 0.f;
    int fc0 = 0, fc1 = 0, fc2 = 0;
    for (int i = threadIdx.x; i < GRID_BLOCKS; i += BLOCK_THREADS) {
        fa0 += g_pa[0][i]; fa1 += g_pa[1][i]; fa2 += g_pa[2][i];
        fc0 += g_pc[0][i]; fc1 += g_pc[1][i]; fc2 += g_pc[2][i];
    }
    fa0 = block_sum_f(fa0, smf);
    fa1 = block_sum_f(fa1, smf);
    fa2 = block_sum_f(fa2, smf);
    fc0 = block_sum_i(fc0, smi);
    fc1 = block_sum_i(fc1, smi);
    fc2 = block_sum_i(fc2, smi);

    if (threadIdx.x == 0) {
        // fc_l == C * sum(M_l) exactly (each mask byte read C times)
        double L = (double)fa0 / (double)fc0 +
                   (double)fa1 / (double)fc1 +
                   (double)fa2 / (double)fc2;
        out[0] = (float)(L / 3.0);
        __threadfence();
        g_ticket = 0;   // restore for next graph replay
    }
}

// ---------------------------------------------------------------------------
extern "C" void kernel_launch(void* const* d_in, const int* in_sizes, int n_in,
                              void* d_out, int out_size) {
    // input order: pred0, true0, pred1, true1, pred2, true2, bboxes, batch_idx, cls
    const float4* p0 = (const float4*)d_in[0];
    const float4* t0 = (const float4*)d_in[1];
    const float4* p1 = (const float4*)d_in[2];
    const float4* t1 = (const float4*)d_in[3];
    const float4* p2 = (const float4*)d_in[4];
    const float4* t2 = (const float4*)d_in[5];
    const float* bboxes = (const float*)d_in[6];
    const int* batch_idx = (const int*)d_in[7];

    mask_kernel<<<dim3(400, 3), 256>>>(bboxes, batch_idx);
    reduce_kernel<<<GRID_BLOCKS, BLOCK_THREADS>>>(p0, t0, p1, t1, p2, t2,
                                                  (float*)d_out);
}

// round 3
// speedup vs baseline: 1.2489x; 1.2489x over previous
#include <cuda_runtime.h>

// ---------------------------------------------------------------------------
// Masked multi-level MSE loss (B=16, C=256, T=128, S in {80,40,20}):
//   L = mean_l [ sum((M_l * (p_l - t_l))^2) / (C * sum(M_l)) ]
//
// 2-kernel pipeline:
//   1) mask_kernel: one block per (batch, level); compacts that batch's boxes
//      into smem (~8 of 128), rasterizes its cells.
//   2) reduce_kernel: streams pred/true unconditionally (mask folded in as a
//      multiply — no load-blocking branch), 2x-unrolled grid-stride loop,
//      accumulates sum-of-squares and mask-byte count (== C*sum(M) exactly);
//      last block finalizes into d_out (self-resetting ticket).
// ---------------------------------------------------------------------------

#define NB 16
#define NT 128
#define NC 256
#define GRID_BLOCKS 1184   // 148 SMs * 8
#define BLOCK_THREADS 256

__device__ unsigned char g_mask0[NB * 80 * 80];
__device__ unsigned char g_mask1[NB * 40 * 40];
__device__ unsigned char g_mask2[NB * 20 * 20];

__device__ float g_pa[3][GRID_BLOCKS];
__device__ int   g_pc[3][GRID_BLOCKS];
__device__ unsigned g_ticket = 0;

// ---------------------------------------------------------------------------
// blockIdx = (cell_chunk, level, batch). Compact this batch's boxes first.
__global__ void mask_kernel(const float* __restrict__ bboxes,
                            const int* __restrict__ batch_idx) {
    const int lvl = blockIdx.y;
    const int b   = blockIdx.z;
    const int S = (lvl == 0) ? 80 : (lvl == 1) ? 40 : 20;
    const int cells = S * S;
    if ((int)(blockIdx.x * blockDim.x) >= cells) return;

    __shared__ int   nb;
    __shared__ short sxl[NT], sxr[NT], syt[NT], syd[NT];

    if (threadIdx.x == 0) nb = 0;
    __syncthreads();
    if (threadIdx.x < NT && batch_idx[threadIdx.x] == b) {
        const int t = threadIdx.x;
        const float fS = (float)S;
        int xc = (int)floorf(bboxes[t * 4 + 0] * fS);
        int yc = (int)floorf(bboxes[t * 4 + 1] * fS);
        int w  = (int)floorf(bboxes[t * 4 + 2] * fS);
        int h  = (int)floorf(bboxes[t * 4 + 3] * fS);
        int slot = atomicAdd(&nb, 1);
        sxl[slot] = (short)max(xc - w / 2, 0);
        syt[slot] = (short)max(yc - h / 2, 0);
        sxr[slot] = (short)min(xc + w / 2, S - 1);
        syd[slot] = (short)min(yc + h / 2, S - 1);
    }
    __syncthreads();

    const int idx = blockIdx.x * blockDim.x + threadIdx.x;
    if (idx < cells) {
        const int y = idx / S;
        const int x = idx % S;
        int m = 0;
        const int n = nb;
        for (int t = 0; t < n; t++) {
            m |= (x >= (int)sxl[t]) & (x <= (int)sxr[t]) &
                 (y >= (int)syt[t]) & (y <= (int)syd[t]);
        }
        unsigned char* mk = (lvl == 0) ? g_mask0 : (lvl == 1) ? g_mask1 : g_mask2;
        mk[b * cells + idx] = (unsigned char)m;
    }
}

// ---------------------------------------------------------------------------
__device__ __forceinline__ float block_sum_f(float v, float* sm) {
#pragma unroll
    for (int o = 16; o; o >>= 1) v += __shfl_down_sync(0xffffffffu, v, o);
    const int lane = threadIdx.x & 31, warp = threadIdx.x >> 5;
    if (lane == 0) sm[warp] = v;
    __syncthreads();
    v = (threadIdx.x < (BLOCK_THREADS / 32)) ? sm[threadIdx.x] : 0.f;
    if (warp == 0) {
#pragma unroll
        for (int o = 16; o; o >>= 1) v += __shfl_down_sync(0xffffffffu, v, o);
    }
    __syncthreads();
    return v;
}

__device__ __forceinline__ int block_sum_i(int v, int* sm) {
#pragma unroll
    for (int o = 16; o; o >>= 1) v += __shfl_down_sync(0xffffffffu, v, o);
    const int lane = threadIdx.x & 31, warp = threadIdx.x >> 5;
    if (lane == 0) sm[warp] = v;
    __syncthreads();
    v = (threadIdx.x < (BLOCK_THREADS / 32)) ? sm[threadIdx.x] : 0;
    if (warp == 0) {
#pragma unroll
        for (int o = 16; o; o >>= 1) v += __shfl_down_sync(0xffffffffu, v, o);
    }
    __syncthreads();
    return v;
}

// ---------------------------------------------------------------------------
template <int S>
__device__ __forceinline__ void level_sumsq(const float4* __restrict__ p,
                                            const float4* __restrict__ q,
                                            const unsigned char* __restrict__ mask,
                                            unsigned gid, unsigned stride,
                                            float& acc_out, int& cnt_out) {
    constexpr unsigned CH4 = (unsigned)S * (S / 4);   // float4 per (b,c) image
    constexpr unsigned B4  = (unsigned)NC * CH4;      // float4 per batch
    constexpr unsigned N4  = (unsigned)NB * B4;       // total float4
    float acc = 0.f;
    int cnt = 0;
    unsigned i = gid;

    // main loop: 2 independent iterations in flight (6 LDG.128 + 2 mask words)
    for (; i + stride < N4; i += 2u * stride) {
        const unsigned i0 = i, i1 = i + stride;
        const unsigned b0 = i0 / B4, r0 = i0 % CH4;
        const unsigned b1 = i1 / B4, r1 = i1 % CH4;
        const uchar4 m0 = *(const uchar4*)(mask + b0 * (unsigned)(S * S) + 4u * r0);
        const uchar4 m1 = *(const uchar4*)(mask + b1 * (unsigned)(S * S) + 4u * r1);
        const float4 a0 = __ldg(&p[i0]);
        const float4 c0 = __ldg(&q[i0]);
        const float4 a1 = __ldg(&p[i1]);
        const float4 c1 = __ldg(&q[i1]);

        cnt += (int)m0.x + (int)m0.y + (int)m0.z + (int)m0.w;
        cnt += (int)m1.x + (int)m1.y + (int)m1.z + (int)m1.w;

        float d;
        d = a0.x - c0.x; acc = fmaf((float)m0.x * d, d, acc);
        d = a0.y - c0.y; acc = fmaf((float)m0.y * d, d, acc);
        d = a0.z - c0.z; acc = fmaf((float)m0.z * d, d, acc);
        d = a0.w - c0.w; acc = fmaf((float)m0.w * d, d, acc);
        d = a1.x - c1.x; acc = fmaf((float)m1.x * d, d, acc);
        d = a1.y - c1.y; acc = fmaf((float)m1.y * d, d, acc);
        d = a1.z - c1.z; acc = fmaf((float)m1.z * d, d, acc);
        d = a1.w - c1.w; acc = fmaf((float)m1.w * d, d, acc);
    }
    if (i < N4) {
        const unsigned b0 = i / B4, r0 = i % CH4;
        const uchar4 m0 = *(const uchar4*)(mask + b0 * (unsigned)(S * S) + 4u * r0);
        const float4 a0 = __ldg(&p[i]);
        const float4 c0 = __ldg(&q[i]);
        cnt += (int)m0.x + (int)m0.y + (int)m0.z + (int)m0.w;
        float d;
        d = a0.x - c0.x; acc = fmaf((float)m0.x * d, d, acc);
        d = a0.y - c0.y; acc = fmaf((float)m0.y * d, d, acc);
        d = a0.z - c0.z; acc = fmaf((float)m0.z * d, d, acc);
        d = a0.w - c0.w; acc = fmaf((float)m0.w * d, d, acc);
    }
    acc_out = acc;
    cnt_out = cnt;
}

// ---------------------------------------------------------------------------
__global__ void __launch_bounds__(BLOCK_THREADS)
reduce_kernel(const float4* __restrict__ p0, const float4* __restrict__ t0,
              const float4* __restrict__ p1, const float4* __restrict__ t1,
              const float4* __restrict__ p2, const float4* __restrict__ t2,
              float* __restrict__ out) {
    const unsigned gid = blockIdx.x * BLOCK_THREADS + threadIdx.x;
    const unsigned stride = GRID_BLOCKS * BLOCK_THREADS;

    float a0, a1, a2;
    int c0, c1, c2;
    level_sumsq<80>(p0, t0, g_mask0, gid, stride, a0, c0);
    level_sumsq<40>(p1, t1, g_mask1, gid, stride, a1, c1);
    level_sumsq<20>(p2, t2, g_mask2, gid, stride, a2, c2);

    __shared__ float smf[32];
    __shared__ int smi[32];
    a0 = block_sum_f(a0, smf);
    a1 = block_sum_f(a1, smf);
    a2 = block_sum_f(a2, smf);
    c0 = block_sum_i(c0, smi);
    c1 = block_sum_i(c1, smi);
    c2 = block_sum_i(c2, smi);

    __shared__ bool s_last;
    if (threadIdx.x == 0) {
        g_pa[0][blockIdx.x] = a0;
        g_pa[1][blockIdx.x] = a1;
        g_pa[2][blockIdx.x] = a2;
        g_pc[0][blockIdx.x] = c0;
        g_pc[1][blockIdx.x] = c1;
        g_pc[2][blockIdx.x] = c2;
        __threadfence();
        unsigned n = atomicAdd(&g_ticket, 1u);
        s_last = (n == GRID_BLOCKS - 1);
    }
    __syncthreads();
    if (!s_last) return;

    // --- finalize (last block only) ---
    float fa0 = 0.f, fa1 = 0.f, fa2 = 0.f;
    int fc0 = 0, fc1 = 0, fc2 = 0;
    for (int i = threadIdx.x; i < GRID_BLOCKS; i += BLOCK_THREADS) {
        fa0 += g_pa[0][i]; fa1 += g_pa[1][i]; fa2 += g_pa[2][i];
        fc0 += g_pc[0][i]; fc1 += g_pc[1][i]; fc2 += g_pc[2][i];
    }
    fa0 = block_sum_f(fa0, smf);
    fa1 = block_sum_f(fa1, smf);
    fa2 = block_sum_f(fa2, smf);
    fc0 = block_sum_i(fc0, smi);
    fc1 = block_sum_i(fc1, smi);
    fc2 = block_sum_i(fc2, smi);

    if (threadIdx.x == 0) {
        double L = (double)fa0 / (double)fc0 +
                   (double)fa1 / (double)fc1 +
                   (double)fa2 / (double)fc2;
        out[0] = (float)(L / 3.0);
        __threadfence();
        g_ticket = 0;   // restore for next graph replay
    }
}

// ---------------------------------------------------------------------------
extern "C" void kernel_launch(void* const* d_in, const int* in_sizes, int n_in,
                              void* d_out, int out_size) {
    // input order: pred0, true0, pred1, true1, pred2, true2, bboxes, batch_idx, cls
    const float4* p0 = (const float4*)d_in[0];
    const float4* t0 = (const float4*)d_in[1];
    const float4* p1 = (const float4*)d_in[2];
    const float4* t1 = (const float4*)d_in[3];
    const float4* p2 = (const float4*)d_in[4];
    const float4* t2 = (const float4*)d_in[5];
    const float* bboxes = (const float*)d_in[6];
    const int* batch_idx = (const int*)d_in[7];

    // 25 chunks covers lvl0 (6400 cells / 256); lvl1/2 chunks early-exit.
    mask_kernel<<<dim3(25, 3, 16), 256>>>(bboxes, batch_idx);
    reduce_kernel<<<GRID_BLOCKS, BLOCK_THREADS>>>(p0, t0, p1, t1, p2, t2,
                                                  (float*)d_out);
}